// round 3
// baseline (speedup 1.0000x reference)
#include <cuda_runtime.h>
#include <cuda_bf16.h>
#include <math.h>

#define NN 50000
#define NE 800000
#define F 64
#define F4 16          // F/4
#define NG 500
#define OUTF 10

// -------- scratch (device globals: no allocation allowed) --------
__device__ float g_dinv[NN];
__device__ int   g_deg[NN];
__device__ int   g_rowptr[NN + 1];
__device__ int   g_pos[NN];
__device__ int   g_csrc[NE];
__device__ float g_h[NN * F];      // X@W result
__device__ float g_feat[NN * F];   // layer output
__device__ float g_pool[NG * F];
__device__ float g_cnt[NG];

// -------- init: zero deg / pool / cnt --------
__global__ void init_kernel() {
    int i = blockIdx.x * blockDim.x + threadIdx.x;
    if (i < NN) g_deg[i] = 0;
    if (i < NG * F) g_pool[i] = 0.0f;
    if (i < NG) g_cnt[i] = 0.0f;
}

// -------- count in-degree (edges only; self-loop added later) --------
__global__ void count_kernel(const int* __restrict__ ei) {
    int e = blockIdx.x * blockDim.x + threadIdx.x;
    if (e >= NE) return;
    int d = ei[NE + e];   // dst row
    atomicAdd(&g_deg[d], 1);
}

// -------- dinv = rsqrt(deg + 1)  (self-loop guarantees >= 1) --------
__global__ void dinv_kernel() {
    int i = blockIdx.x * blockDim.x + threadIdx.x;
    if (i >= NN) return;
    g_dinv[i] = rsqrtf((float)(g_deg[i] + 1));
}

// -------- single-block prefix scan -> rowptr / pos --------
__global__ void scan_kernel() {
    __shared__ int sums[1024];
    const int CH = (NN + 1023) / 1024;   // 49
    int t = threadIdx.x;
    int base = t * CH;
    int s = 0;
    for (int i = 0; i < CH; i++) {
        int idx = base + i;
        if (idx < NN) s += g_deg[idx];
    }
    sums[t] = s;
    __syncthreads();
    for (int off = 1; off < 1024; off <<= 1) {
        int v = (t >= off) ? sums[t - off] : 0;
        __syncthreads();
        sums[t] += v;
        __syncthreads();
    }
    int run = (t == 0) ? 0 : sums[t - 1];
    for (int i = 0; i < CH; i++) {
        int idx = base + i;
        if (idx < NN) {
            g_rowptr[idx] = run;
            g_pos[idx] = run;
            run += g_deg[idx];
        }
    }
    if (t == 1023) g_rowptr[NN] = sums[1023];
}

// -------- scatter edges into CSR (counting sort by dst) --------
__global__ void scatter_kernel(const int* __restrict__ ei) {
    int e = blockIdx.x * blockDim.x + threadIdx.x;
    if (e >= NE) return;
    int s = ei[e];
    int d = ei[NE + e];
    int idx = atomicAdd(&g_pos[d], 1);
    g_csrc[idx] = s;
}

// -------- GEMM: g_h[n,64] = X[n,64] @ W[64,64]  --------
// X == nullptr means "read from g_feat" (layer 2).
__global__ __launch_bounds__(256) void gemm64_kernel(
    const float* __restrict__ X, const float* __restrict__ W)
{
    __shared__ float4 Ws[64][16];
    __shared__ float  Xs[16][65];   // pad to kill bank conflicts

    const float* Xp = X ? X : g_feat;

    int tid = threadIdx.x;
    const float4* W4 = (const float4*)W;
    #pragma unroll
    for (int i = tid; i < 64 * 16; i += 256)
        Ws[i >> 4][i & 15] = W4[i];

    int row0 = blockIdx.x * 16;
    {
        int r = tid >> 4, c4 = tid & 15;
        float4 v = ((const float4*)Xp)[(row0 + r) * F4 + c4];
        Xs[r][c4 * 4 + 0] = v.x;
        Xs[r][c4 * 4 + 1] = v.y;
        Xs[r][c4 * 4 + 2] = v.z;
        Xs[r][c4 * 4 + 3] = v.w;
    }
    __syncthreads();

    int r = tid >> 4, cg = tid & 15;
    float4 acc = make_float4(0.f, 0.f, 0.f, 0.f);
    #pragma unroll
    for (int k = 0; k < 64; k++) {
        float xv = Xs[r][k];
        float4 w = Ws[k][cg];
        acc.x += xv * w.x;
        acc.y += xv * w.y;
        acc.z += xv * w.z;
        acc.w += xv * w.w;
    }
    ((float4*)g_h)[(row0 + r) * F4 + cg] = acc;
}

// -------- aggregation: g_feat[i] = relu( sum_{e: dst=i} g_h[src]*dinv[s]*dinv[i]
//                                        + g_h[i]*dinv[i]^2 + b ) --------
__global__ __launch_bounds__(256) void agg_kernel(const float* __restrict__ bias) {
    int node = blockIdx.x * 16 + (threadIdx.x >> 4);
    int t = threadIdx.x & 15;
    if (node >= NN) return;

    float di = g_dinv[node];
    float4 acc = make_float4(0.f, 0.f, 0.f, 0.f);
    int beg = g_rowptr[node];
    int end = g_rowptr[node + 1];
    const float4* H = (const float4*)g_h;

    for (int j = beg; j < end; j++) {
        int s = g_csrc[j];
        float w = g_dinv[s] * di;
        float4 hv = H[s * F4 + t];
        acc.x += hv.x * w;
        acc.y += hv.y * w;
        acc.z += hv.z * w;
        acc.w += hv.w * w;
    }
    // self loop
    {
        float4 hv = H[node * F4 + t];
        float w = di * di;
        acc.x += hv.x * w;
        acc.y += hv.y * w;
        acc.z += hv.z * w;
        acc.w += hv.w * w;
    }
    float4 b = ((const float4*)bias)[t];
    float4 o;
    o.x = fmaxf(acc.x + b.x, 0.f);
    o.y = fmaxf(acc.y + b.y, 0.f);
    o.z = fmaxf(acc.z + b.z, 0.f);
    o.w = fmaxf(acc.w + b.w, 0.f);
    ((float4*)g_feat)[node * F4 + t] = o;
}

// -------- global mean pool (sum + count via atomics) --------
__global__ __launch_bounds__(256) void pool_kernel(const int* __restrict__ batch) {
    int node = blockIdx.x * 16 + (threadIdx.x >> 4);
    int t = threadIdx.x & 15;
    if (node >= NN) return;
    int g = batch[node];
    float4 v = ((const float4*)g_feat)[node * F4 + t];
    float* p = &g_pool[g * F + t * 4];
    atomicAdd(p + 0, v.x);
    atomicAdd(p + 1, v.y);
    atomicAdd(p + 2, v.z);
    atomicAdd(p + 3, v.w);
    if (t == 0) atomicAdd(&g_cnt[g], 1.0f);
}

// -------- head: pooled@Wc + bc, log_softmax --------
__global__ __launch_bounds__(64) void head_kernel(
    const float* __restrict__ Wc, const float* __restrict__ bc,
    float* __restrict__ out)
{
    __shared__ float p[64];
    __shared__ float lg[OUTF];
    __shared__ float red[2];
    int g = blockIdx.x;
    int t = threadIdx.x;
    float c = fmaxf(g_cnt[g], 1.0f);
    p[t] = g_pool[g * F + t] / c;
    __syncthreads();
    if (t < OUTF) {
        float acc = bc[t];
        #pragma unroll
        for (int k = 0; k < 64; k++)
            acc += p[k] * Wc[k * OUTF + t];
        lg[t] = acc;
    }
    __syncthreads();
    if (t == 0) {
        float m = -1e30f;
        #pragma unroll
        for (int i = 0; i < OUTF; i++) m = fmaxf(m, lg[i]);
        float s = 0.f;
        #pragma unroll
        for (int i = 0; i < OUTF; i++) s += expf(lg[i] - m);
        red[0] = m;
        red[1] = logf(s);
    }
    __syncthreads();
    if (t < OUTF) out[g * OUTF + t] = lg[t] - red[0] - red[1];
}

extern "C" void kernel_launch(void* const* d_in, const int* in_sizes, int n_in,
                              void* d_out, int out_size) {
    const float* x     = (const float*)d_in[0];
    const int*   ei    = (const int*)d_in[1];
    const int*   batch = (const int*)d_in[2];
    const float* W1    = (const float*)d_in[3];
    const float* b1    = (const float*)d_in[4];
    const float* W2    = (const float*)d_in[5];
    const float* b2    = (const float*)d_in[6];
    const float* Wc    = (const float*)d_in[7];
    const float* bc    = (const float*)d_in[8];
    float* out = (float*)d_out;

    const int EB = (NE + 255) / 256;
    const int NB = (NN + 255) / 256;
    const int NODE_B = (NN + 15) / 16;     // 3125 blocks, 16 nodes/block
    const int IB = ((NG * F + 255) / 256 > NB) ? (NG * F + 255) / 256 : NB;

    // build degree / CSR
    init_kernel<<<IB, 256>>>();
    count_kernel<<<EB, 256>>>(ei);
    dinv_kernel<<<NB, 256>>>();
    scan_kernel<<<1, 1024>>>();
    scatter_kernel<<<EB, 256>>>(ei);

    // layer 1
    gemm64_kernel<<<NODE_B, 256>>>(x, W1);
    agg_kernel<<<NODE_B, 256>>>(b1);

    // layer 2
    gemm64_kernel<<<NODE_B, 256>>>(nullptr, W2);
    agg_kernel<<<NODE_B, 256>>>(b2);

    // pool + head
    pool_kernel<<<NODE_B, 256>>>(batch);
    head_kernel<<<NG, 64>>>(Wc, bc, out);
}

// round 4
// speedup vs baseline: 1.4500x; 1.4500x over previous
#include <cuda_runtime.h>
#include <cuda_bf16.h>
#include <math.h>

#define NN 50000
#define NE 800000
#define F 64
#define F4 16          // F/4
#define NG 500
#define OUTF 10
#define SCAN_B ((NN + 255) / 256)   // 196 blocks

// -------- scratch (device globals: no allocation allowed) --------
__device__ float g_dinv[NN];
__device__ int   g_deg[NN];
__device__ int   g_rowptr[NN + 1];
__device__ int   g_pos[NN];
__device__ int   g_bsum[SCAN_B];
__device__ int   g_boff[SCAN_B];
__device__ int   g_csrc[NE];
__device__ float g_h[NN * F];      // X@W result
__device__ float g_feat[NN * F];   // layer output
__device__ float g_pool[NG * F];
__device__ float g_cnt[NG];

// -------- init: zero deg / pool / cnt --------
__global__ void init_kernel() {
    int i = blockIdx.x * blockDim.x + threadIdx.x;
    if (i < NN) g_deg[i] = 0;
    if (i < NG * F) g_pool[i] = 0.0f;
    if (i < NG) g_cnt[i] = 0.0f;
}

// -------- count in-degree (edges only; self-loop added later) --------
__global__ void count_kernel(const int* __restrict__ ei) {
    int e = blockIdx.x * blockDim.x + threadIdx.x;
    if (e >= NE) return;
    int d = ei[NE + e];   // dst row
    atomicAdd(&g_deg[d], 1);
}

// -------- dinv = rsqrt(deg + 1)  (self-loop guarantees >= 1) --------
__global__ void dinv_kernel() {
    int i = blockIdx.x * blockDim.x + threadIdx.x;
    if (i >= NN) return;
    g_dinv[i] = rsqrtf((float)(g_deg[i] + 1));
}

// -------- hierarchical scan, phase 1: per-block exclusive scan + block sum --------
__global__ __launch_bounds__(256) void scan1_kernel() {
    __shared__ int s[256];
    int t = threadIdx.x;
    int idx = blockIdx.x * 256 + t;
    int v = (idx < NN) ? g_deg[idx] : 0;
    s[t] = v;
    __syncthreads();
    #pragma unroll
    for (int off = 1; off < 256; off <<= 1) {
        int u = (t >= off) ? s[t - off] : 0;
        __syncthreads();
        s[t] += u;
        __syncthreads();
    }
    if (idx < NN) g_rowptr[idx] = s[t] - v;   // exclusive within block
    if (t == 255) g_bsum[blockIdx.x] = s[255];
}

// -------- phase 2: exclusive scan of the 196 block sums (one block) --------
__global__ __launch_bounds__(256) void scan2_kernel() {
    __shared__ int s[256];
    int t = threadIdx.x;
    int v = (t < SCAN_B) ? g_bsum[t] : 0;
    s[t] = v;
    __syncthreads();
    #pragma unroll
    for (int off = 1; off < 256; off <<= 1) {
        int u = (t >= off) ? s[t - off] : 0;
        __syncthreads();
        s[t] += u;
        __syncthreads();
    }
    if (t < SCAN_B) g_boff[t] = s[t] - v;
}

// -------- phase 3: apply offsets; rowptr[NN] = NE is constant --------
__global__ __launch_bounds__(256) void scan3_kernel() {
    int idx = blockIdx.x * 256 + threadIdx.x;
    if (idx >= NN) return;
    int rp = g_rowptr[idx] + g_boff[blockIdx.x];
    g_rowptr[idx] = rp;
    g_pos[idx] = rp;
    if (idx == 0) g_rowptr[NN] = NE;
}

// -------- scatter edges into CSR (counting sort by dst) --------
__global__ void scatter_kernel(const int* __restrict__ ei) {
    int e = blockIdx.x * blockDim.x + threadIdx.x;
    if (e >= NE) return;
    int s = ei[e];
    int d = ei[NE + e];
    int idx = atomicAdd(&g_pos[d], 1);
    g_csrc[idx] = s;
}

// -------- GEMM: g_h[n,64] = X[n,64] @ W[64,64]  --------
// X == nullptr means "read from g_feat" (layer 2).
__global__ __launch_bounds__(256) void gemm64_kernel(
    const float* __restrict__ X, const float* __restrict__ W)
{
    __shared__ float4 Ws[64][16];
    __shared__ float  Xs[16][65];   // pad to kill bank conflicts

    const float* Xp = X ? X : g_feat;

    int tid = threadIdx.x;
    const float4* W4 = (const float4*)W;
    #pragma unroll
    for (int i = tid; i < 64 * 16; i += 256)
        Ws[i >> 4][i & 15] = W4[i];

    int row0 = blockIdx.x * 16;
    {
        int r = tid >> 4, c4 = tid & 15;
        float4 v = ((const float4*)Xp)[(row0 + r) * F4 + c4];
        Xs[r][c4 * 4 + 0] = v.x;
        Xs[r][c4 * 4 + 1] = v.y;
        Xs[r][c4 * 4 + 2] = v.z;
        Xs[r][c4 * 4 + 3] = v.w;
    }
    __syncthreads();

    int r = tid >> 4, cg = tid & 15;
    float4 acc = make_float4(0.f, 0.f, 0.f, 0.f);
    #pragma unroll
    for (int k = 0; k < 64; k++) {
        float xv = Xs[r][k];
        float4 w = Ws[k][cg];
        acc.x += xv * w.x;
        acc.y += xv * w.y;
        acc.z += xv * w.z;
        acc.w += xv * w.w;
    }
    ((float4*)g_h)[(row0 + r) * F4 + cg] = acc;
}

// -------- aggregation: g_feat[i] = relu( sum_{e: dst=i} g_h[src]*dinv[s]*dinv[i]
//                                        + g_h[i]*dinv[i]^2 + b ) --------
// 16 threads (float4 lanes) per node, no atomics. Edge loop unrolled x2 for MLP.
__global__ __launch_bounds__(256) void agg_kernel(const float* __restrict__ bias) {
    int node = blockIdx.x * 16 + (threadIdx.x >> 4);
    int t = threadIdx.x & 15;
    if (node >= NN) return;

    float di = g_dinv[node];
    float4 acc = make_float4(0.f, 0.f, 0.f, 0.f);
    float4 acc2 = make_float4(0.f, 0.f, 0.f, 0.f);
    int beg = g_rowptr[node];
    int end = g_rowptr[node + 1];
    const float4* H = (const float4*)g_h;

    int j = beg;
    for (; j + 2 <= end; j += 2) {
        int s0 = g_csrc[j];
        int s1 = g_csrc[j + 1];
        float w0 = g_dinv[s0];
        float w1 = g_dinv[s1];
        float4 h0 = H[s0 * F4 + t];
        float4 h1 = H[s1 * F4 + t];
        acc.x += h0.x * w0;  acc.y += h0.y * w0;
        acc.z += h0.z * w0;  acc.w += h0.w * w0;
        acc2.x += h1.x * w1; acc2.y += h1.y * w1;
        acc2.z += h1.z * w1; acc2.w += h1.w * w1;
    }
    if (j < end) {
        int s0 = g_csrc[j];
        float w0 = g_dinv[s0];
        float4 h0 = H[s0 * F4 + t];
        acc.x += h0.x * w0;  acc.y += h0.y * w0;
        acc.z += h0.z * w0;  acc.w += h0.w * w0;
    }
    acc.x += acc2.x; acc.y += acc2.y; acc.z += acc2.z; acc.w += acc2.w;
    // edge sum is scaled by di; self loop contributes h[i]*di^2
    {
        float4 hv = H[node * F4 + t];
        acc.x = (acc.x + hv.x * di) * di;
        acc.y = (acc.y + hv.y * di) * di;
        acc.z = (acc.z + hv.z * di) * di;
        acc.w = (acc.w + hv.w * di) * di;
    }
    float4 b = ((const float4*)bias)[t];
    float4 o;
    o.x = fmaxf(acc.x + b.x, 0.f);
    o.y = fmaxf(acc.y + b.y, 0.f);
    o.z = fmaxf(acc.z + b.z, 0.f);
    o.w = fmaxf(acc.w + b.w, 0.f);
    ((float4*)g_feat)[node * F4 + t] = o;
}

// -------- global mean pool (sum + count via atomics) --------
__global__ __launch_bounds__(256) void pool_kernel(const int* __restrict__ batch) {
    int node = blockIdx.x * 16 + (threadIdx.x >> 4);
    int t = threadIdx.x & 15;
    if (node >= NN) return;
    int g = batch[node];
    float4 v = ((const float4*)g_feat)[node * F4 + t];
    float* p = &g_pool[g * F + t * 4];
    atomicAdd(p + 0, v.x);
    atomicAdd(p + 1, v.y);
    atomicAdd(p + 2, v.z);
    atomicAdd(p + 3, v.w);
    if (t == 0) atomicAdd(&g_cnt[g], 1.0f);
}

// -------- head: pooled@Wc + bc, log_softmax --------
__global__ __launch_bounds__(64) void head_kernel(
    const float* __restrict__ Wc, const float* __restrict__ bc,
    float* __restrict__ out)
{
    __shared__ float p[64];
    __shared__ float lg[OUTF];
    __shared__ float red[2];
    int g = blockIdx.x;
    int t = threadIdx.x;
    float c = fmaxf(g_cnt[g], 1.0f);
    p[t] = g_pool[g * F + t] / c;
    __syncthreads();
    if (t < OUTF) {
        float acc = bc[t];
        #pragma unroll
        for (int k = 0; k < 64; k++)
            acc += p[k] * Wc[k * OUTF + t];
        lg[t] = acc;
    }
    __syncthreads();
    if (t == 0) {
        float m = -1e30f;
        #pragma unroll
        for (int i = 0; i < OUTF; i++) m = fmaxf(m, lg[i]);
        float s = 0.f;
        #pragma unroll
        for (int i = 0; i < OUTF; i++) s += expf(lg[i] - m);
        red[0] = m;
        red[1] = logf(s);
    }
    __syncthreads();
    if (t < OUTF) out[g * OUTF + t] = lg[t] - red[0] - red[1];
}

extern "C" void kernel_launch(void* const* d_in, const int* in_sizes, int n_in,
                              void* d_out, int out_size) {
    const float* x     = (const float*)d_in[0];
    const int*   ei    = (const int*)d_in[1];
    const int*   batch = (const int*)d_in[2];
    const float* W1    = (const float*)d_in[3];
    const float* b1    = (const float*)d_in[4];
    const float* W2    = (const float*)d_in[5];
    const float* b2    = (const float*)d_in[6];
    const float* Wc    = (const float*)d_in[7];
    const float* bc    = (const float*)d_in[8];
    float* out = (float*)d_out;

    const int EB = (NE + 255) / 256;
    const int NODE_B = (NN + 15) / 16;     // 3125 blocks, 16 nodes/block
    const int NB = SCAN_B;
    const int IB = ((NG * F + 255) / 256 > NB) ? (NG * F + 255) / 256 : NB;

    // build degree / CSR
    init_kernel<<<IB, 256>>>();
    count_kernel<<<EB, 256>>>(ei);
    dinv_kernel<<<NB, 256>>>();
    scan1_kernel<<<SCAN_B, 256>>>();
    scan2_kernel<<<1, 256>>>();
    scan3_kernel<<<SCAN_B, 256>>>();
    scatter_kernel<<<EB, 256>>>(ei);

    // layer 1
    gemm64_kernel<<<NODE_B, 256>>>(x, W1);
    agg_kernel<<<NODE_B, 256>>>(b1);

    // layer 2
    gemm64_kernel<<<NODE_B, 256>>>(nullptr, W2);
    agg_kernel<<<NODE_B, 256>>>(b2);

    // pool + head
    pool_kernel<<<NODE_B, 256>>>(batch);
    head_kernel<<<NG, 64>>>(Wc, bc, out);
}

// round 5
// speedup vs baseline: 1.6503x; 1.1381x over previous
#include <cuda_runtime.h>
#include <cuda_bf16.h>
#include <cuda_fp16.h>
#include <math.h>

#define NN 50000
#define NE 800000
#define F 64
#define F4 16          // F/4
#define NG 500
#define OUTF 10
#define SCAN_B ((NN + 255) / 256)   // 196 blocks

// -------- scratch (device globals: no allocation allowed) --------
__device__ float  g_dinv[NN];
__device__ int    g_deg[NN];
__device__ int    g_rowptr[NN + 1];
__device__ int    g_pos[NN];
__device__ int    g_bsum[SCAN_B];
__device__ int    g_boff[SCAN_B];
__device__ int    g_csrc[NE];
__device__ __half g_hs[NN * F];    // (X@W) * dinv[row], fp16 (128B/row)
__device__ float  g_feat[NN * F];  // layer-1 output (fp32)
__device__ float  g_pool[NG * F];
__device__ float  g_cnt[NG];

// -------- init: zero deg / pool / cnt --------
__global__ void init_kernel() {
    int i = blockIdx.x * blockDim.x + threadIdx.x;
    if (i < NN) g_deg[i] = 0;
    if (i < NG * F) g_pool[i] = 0.0f;
    if (i < NG) g_cnt[i] = 0.0f;
}

// -------- count in-degree (edges only; self-loop added later) --------
__global__ void count_kernel(const int* __restrict__ ei) {
    int e = blockIdx.x * blockDim.x + threadIdx.x;
    if (e >= NE) return;
    atomicAdd(&g_deg[ei[NE + e]], 1);
}

// -------- scan phase 1: per-block exclusive scan + block sum; fused dinv --------
__global__ __launch_bounds__(256) void scan1_kernel() {
    __shared__ int s[256];
    int t = threadIdx.x;
    int idx = blockIdx.x * 256 + t;
    int v = (idx < NN) ? g_deg[idx] : 0;
    if (idx < NN) g_dinv[idx] = rsqrtf((float)(v + 1));
    s[t] = v;
    __syncthreads();
    #pragma unroll
    for (int off = 1; off < 256; off <<= 1) {
        int u = (t >= off) ? s[t - off] : 0;
        __syncthreads();
        s[t] += u;
        __syncthreads();
    }
    if (idx < NN) g_rowptr[idx] = s[t] - v;   // exclusive within block
    if (t == 255) g_bsum[blockIdx.x] = s[255];
}

// -------- phase 2: exclusive scan of the block sums (one block) --------
__global__ __launch_bounds__(256) void scan2_kernel() {
    __shared__ int s[256];
    int t = threadIdx.x;
    int v = (t < SCAN_B) ? g_bsum[t] : 0;
    s[t] = v;
    __syncthreads();
    #pragma unroll
    for (int off = 1; off < 256; off <<= 1) {
        int u = (t >= off) ? s[t - off] : 0;
        __syncthreads();
        s[t] += u;
        __syncthreads();
    }
    if (t < SCAN_B) g_boff[t] = s[t] - v;
}

// -------- phase 3: apply offsets; rowptr[NN] = NE is constant --------
__global__ __launch_bounds__(256) void scan3_kernel() {
    int idx = blockIdx.x * 256 + threadIdx.x;
    if (idx >= NN) return;
    int rp = g_rowptr[idx] + g_boff[blockIdx.x];
    g_rowptr[idx] = rp;
    g_pos[idx] = rp;
    if (idx == 0) g_rowptr[NN] = NE;
}

// -------- scatter edges into CSR (counting sort by dst) --------
__global__ void scatter_kernel(const int* __restrict__ ei) {
    int e = blockIdx.x * blockDim.x + threadIdx.x;
    if (e >= NE) return;
    int s = ei[e];
    int d = ei[NE + e];
    g_csrc[atomicAdd(&g_pos[d], 1)] = s;
}

// -------- GEMM: g_hs[n,64] = fp16( (X[n,64] @ W[64,64]) * dinv[n] ) --------
// X == nullptr means "read from g_feat" (layer 2).
__global__ __launch_bounds__(256) void gemm64_kernel(
    const float* __restrict__ X, const float* __restrict__ W)
{
    __shared__ float4 Ws[64][16];
    __shared__ float  Xs[16][65];   // pad to kill bank conflicts

    const float* Xp = X ? X : g_feat;

    int tid = threadIdx.x;
    const float4* W4 = (const float4*)W;
    #pragma unroll
    for (int i = tid; i < 64 * 16; i += 256)
        Ws[i >> 4][i & 15] = W4[i];

    int row0 = blockIdx.x * 16;
    {
        int r = tid >> 4, c4 = tid & 15;
        float4 v = ((const float4*)Xp)[(row0 + r) * F4 + c4];
        Xs[r][c4 * 4 + 0] = v.x;
        Xs[r][c4 * 4 + 1] = v.y;
        Xs[r][c4 * 4 + 2] = v.z;
        Xs[r][c4 * 4 + 3] = v.w;
    }
    __syncthreads();

    int r = tid >> 4, cg = tid & 15;
    float4 acc = make_float4(0.f, 0.f, 0.f, 0.f);
    #pragma unroll
    for (int k = 0; k < 64; k++) {
        float xv = Xs[r][k];
        float4 w = Ws[k][cg];
        acc.x += xv * w.x;
        acc.y += xv * w.y;
        acc.z += xv * w.z;
        acc.w += xv * w.w;
    }
    float di = g_dinv[row0 + r];
    __half2 p0 = __floats2half2_rn(acc.x * di, acc.y * di);
    __half2 p1 = __floats2half2_rn(acc.z * di, acc.w * di);
    uint2 pk;
    pk.x = *(unsigned*)&p0;
    pk.y = *(unsigned*)&p1;
    ((uint2*)g_hs)[(row0 + r) * F4 + cg] = pk;
}

// -------- aggregation: out[i] = relu( (sum_{src} hs[src] + hs[i]) * dinv[i] + b )
// 16 threads per node (8B fp16x4 lanes), no atomics, unroll x2.
// POOL: atomically accumulate into g_pool instead of writing g_feat.
template <bool POOL>
__global__ __launch_bounds__(256) void agg_kernel(
    const float* __restrict__ bias, const int* __restrict__ batch)
{
    int node = blockIdx.x * 16 + (threadIdx.x >> 4);
    int t = threadIdx.x & 15;
    if (node >= NN) return;

    float di = g_dinv[node];
    float4 acc = make_float4(0.f, 0.f, 0.f, 0.f);
    float4 acc2 = make_float4(0.f, 0.f, 0.f, 0.f);
    int beg = g_rowptr[node];
    int end = g_rowptr[node + 1];
    const uint2* HS = (const uint2*)g_hs;

    int j = beg;
    for (; j + 2 <= end; j += 2) {
        int s0 = g_csrc[j];
        int s1 = g_csrc[j + 1];
        uint2 p0 = HS[s0 * F4 + t];
        uint2 p1 = HS[s1 * F4 + t];
        float2 a0 = __half22float2(*(__half2*)&p0.x);
        float2 a1 = __half22float2(*(__half2*)&p0.y);
        float2 b0 = __half22float2(*(__half2*)&p1.x);
        float2 b1 = __half22float2(*(__half2*)&p1.y);
        acc.x += a0.x;  acc.y += a0.y;  acc.z += a1.x;  acc.w += a1.y;
        acc2.x += b0.x; acc2.y += b0.y; acc2.z += b1.x; acc2.w += b1.y;
    }
    if (j < end) {
        int s0 = g_csrc[j];
        uint2 p0 = HS[s0 * F4 + t];
        float2 a0 = __half22float2(*(__half2*)&p0.x);
        float2 a1 = __half22float2(*(__half2*)&p0.y);
        acc.x += a0.x; acc.y += a0.y; acc.z += a1.x; acc.w += a1.y;
    }
    // self loop
    {
        uint2 p0 = HS[node * F4 + t];
        float2 a0 = __half22float2(*(__half2*)&p0.x);
        float2 a1 = __half22float2(*(__half2*)&p0.y);
        acc.x += acc2.x + a0.x;
        acc.y += acc2.y + a0.y;
        acc.z += acc2.z + a1.x;
        acc.w += acc2.w + a1.y;
    }
    float4 b = ((const float4*)bias)[t];
    float4 o;
    o.x = fmaxf(acc.x * di + b.x, 0.f);
    o.y = fmaxf(acc.y * di + b.y, 0.f);
    o.z = fmaxf(acc.z * di + b.z, 0.f);
    o.w = fmaxf(acc.w * di + b.w, 0.f);

    if (POOL) {
        int g = batch[node];
        float* p = &g_pool[g * F + t * 4];
        atomicAdd(p + 0, o.x);
        atomicAdd(p + 1, o.y);
        atomicAdd(p + 2, o.z);
        atomicAdd(p + 3, o.w);
        if (t == 0) atomicAdd(&g_cnt[g], 1.0f);
    } else {
        ((float4*)g_feat)[node * F4 + t] = o;
    }
}

// -------- head: pooled@Wc + bc, log_softmax --------
__global__ __launch_bounds__(64) void head_kernel(
    const float* __restrict__ Wc, const float* __restrict__ bc,
    float* __restrict__ out)
{
    __shared__ float p[64];
    __shared__ float lg[OUTF];
    __shared__ float red[2];
    int g = blockIdx.x;
    int t = threadIdx.x;
    float c = fmaxf(g_cnt[g], 1.0f);
    p[t] = g_pool[g * F + t] / c;
    __syncthreads();
    if (t < OUTF) {
        float acc = bc[t];
        #pragma unroll
        for (int k = 0; k < 64; k++)
            acc += p[k] * Wc[k * OUTF + t];
        lg[t] = acc;
    }
    __syncthreads();
    if (t == 0) {
        float m = -1e30f;
        #pragma unroll
        for (int i = 0; i < OUTF; i++) m = fmaxf(m, lg[i]);
        float s = 0.f;
        #pragma unroll
        for (int i = 0; i < OUTF; i++) s += expf(lg[i] - m);
        red[0] = m;
        red[1] = logf(s);
    }
    __syncthreads();
    if (t < OUTF) out[g * OUTF + t] = lg[t] - red[0] - red[1];
}

extern "C" void kernel_launch(void* const* d_in, const int* in_sizes, int n_in,
                              void* d_out, int out_size) {
    const float* x     = (const float*)d_in[0];
    const int*   ei    = (const int*)d_in[1];
    const int*   batch = (const int*)d_in[2];
    const float* W1    = (const float*)d_in[3];
    const float* b1    = (const float*)d_in[4];
    const float* W2    = (const float*)d_in[5];
    const float* b2    = (const float*)d_in[6];
    const float* Wc    = (const float*)d_in[7];
    const float* bc    = (const float*)d_in[8];
    float* out = (float*)d_out;

    const int EB = (NE + 255) / 256;
    const int NODE_B = (NN + 15) / 16;     // 3125 blocks, 16 nodes/block
    const int IB = ((NG * F + 255) / 256 > SCAN_B) ? (NG * F + 255) / 256 : SCAN_B;

    // build degree / CSR
    init_kernel<<<IB, 256>>>();
    count_kernel<<<EB, 256>>>(ei);
    scan1_kernel<<<SCAN_B, 256>>>();
    scan2_kernel<<<1, 256>>>();
    scan3_kernel<<<SCAN_B, 256>>>();
    scatter_kernel<<<EB, 256>>>(ei);

    // layer 1
    gemm64_kernel<<<NODE_B, 256>>>(x, W1);
    agg_kernel<false><<<NODE_B, 256>>>(b1, batch);

    // layer 2 (pool fused into agg)
    gemm64_kernel<<<NODE_B, 256>>>(nullptr, W2);
    agg_kernel<true><<<NODE_B, 256>>>(b2, batch);

    // head
    head_kernel<<<NG, 64>>>(Wc, bc, out);
}